// round 15
// baseline (speedup 1.0000x reference)
#include <cuda_runtime.h>
#include <cuda_bf16.h>
#include <math.h>
#include <stdint.h>

#define Bn 64
#define Hn 512
#define En 256
#define Vn 32000
#define Sn 64
#define NVB 250       /* Vn / 128 v-blocks in logits kernel */
#define NKT 32        /* logits k-tiles of 16 (Hn/16) */
#define GKT 48        /* gates  k-tiles of 16 ((En+Hn)/16) */
#define GSL 6         /* gates k-slices total (2 x + 4 h) */
#define GKS 8         /* k-tiles per slice */

// ---------------- persistent device state (no cudaMalloc allowed) ------------
__device__ float g_c[Bn * Hn];
__device__ float g_gates[16 * 128 * Bn];   // [bid][row_local][b] fp32 partials
__device__ int   g_cnt[16];                // split-K completion counters
__device__ float g_pval[Bn * NVB];
__device__ int   g_pidx[Bn * NVB];
__device__ int   g_tf[Sn];

// logits W fragments, fp32 (hi+lo derived in-kernel): [mtile(2000)][kt(32)][lane(32)][8 f32]
__device__ float g_wfrag32[(size_t)Vn * Hn];
// gates W fragments (bf16 hi/lo; small, L2-resident)
__device__ __nv_bfloat16 g_wg_hi[(size_t)128 * GKT * 32 * 8];
__device__ __nv_bfloat16 g_wg_lo[(size_t)128 * GKT * 32 * 8];
// h B-fragments, double buffered: [buf][ntile(8)][ktile(32)][lane(32)][4 bf16]
__device__ __nv_bfloat16 g_hfrag_hi[2][Bn * Hn];
__device__ __nv_bfloat16 g_hfrag_lo[2][Bn * Hn];

__device__ __forceinline__ float sigmoidf_(float x) {
    return 1.0f / (1.0f + expf(-x));
}

__device__ __forceinline__ void mma16816(float* c, const uint4& a, const uint2& b) {
    asm volatile(
        "mma.sync.aligned.m16n8k16.row.col.f32.bf16.bf16.f32 "
        "{%0,%1,%2,%3}, {%4,%5,%6,%7}, {%8,%9}, {%0,%1,%2,%3};"
        : "+f"(c[0]), "+f"(c[1]), "+f"(c[2]), "+f"(c[3])
        : "r"(a.x), "r"(a.y), "r"(a.z), "r"(a.w), "r"(b.x), "r"(b.y));
}

// pack two f32 into bf16x2 (w1 -> high, w0 -> low), round-to-nearest
__device__ __forceinline__ uint32_t cvt2(float w1, float w0) {
    uint32_t r;
    asm("cvt.rn.bf16x2.f32 %0, %1, %2;" : "=r"(r) : "f"(w1), "f"(w0));
    return r;
}
// given packed hi and the two fp32 sources, produce packed lo residual
__device__ __forceinline__ uint32_t lo2(uint32_t hi2, float w0, float w1) {
    float h0 = __uint_as_float(hi2 << 16);
    float h1 = __uint_as_float(hi2 & 0xffff0000u);
    return cvt2(w1 - h1, w0 - h0);
}

// ---------------- one-time conversions ---------------------------------------
__global__ void convert_w32_kernel(const float* __restrict__ fc_w) {
    size_t idx = (size_t)blockIdx.x * blockDim.x + threadIdx.x;
    if (idx >= (size_t)Vn * Hn) return;
    int v = (int)(idx >> 9);
    int kg = (int)(idx & 511);
    int mtile = v >> 4, r = v & 15;
    int ktile = kg >> 4, c = kg & 15;
    int lane = (r & 7) * 4 + ((c & 7) >> 1);
    int reg  = (r >> 3) + 2 * (c >> 3);
    int pos  = c & 1;
    size_t off = ((size_t)(mtile * NKT + ktile) * 32 + lane) * 8 + reg * 2 + pos;
    g_wfrag32[off] = fc_w[idx];
}

__global__ void convert_wg_kernel(const float* __restrict__ W_ih,
                                  const float* __restrict__ W_hh) {
    size_t idx = (size_t)blockIdx.x * blockDim.x + threadIdx.x;
    if (idx >= (size_t)2048 * 768) return;
    int R = (int)(idx / 768);
    int kc = (int)(idx % 768);
    float w = (kc < En) ? W_ih[(size_t)R * En + kc]
                        : W_hh[(size_t)R * Hn + (kc - En)];
    __nv_bfloat16 hi = __float2bfloat16(w);
    __nv_bfloat16 lo = __float2bfloat16(w - __bfloat162float(hi));
    int gate = R >> 9, j = R & 511;
    int bid = j >> 5;
    int rloc = gate * 32 + (j & 31);
    int mtile = bid * 8 + (rloc >> 4);
    int r16 = rloc & 15;
    int ktile = kc >> 4, c = kc & 15;
    int lane = (r16 & 7) * 4 + ((c & 7) >> 1);
    int reg  = (r16 >> 3) + 2 * (c >> 3);
    int pos  = c & 1;
    size_t off = ((size_t)(mtile * GKT + ktile) * 32 + lane) * 8 + reg * 2 + pos;
    g_wg_hi[off] = hi;
    g_wg_lo[off] = lo;
}

// one-time: h fragments from encoder_hidden into buffer 0
__global__ __launch_bounds__(256) void encfrag_kernel(const float* __restrict__ enc) {
    int b = blockIdx.x;
    int tid = threadIdx.x;
    #pragma unroll
    for (int q = 0; q < 2; q++) {
        int j = tid + q * 256;
        float h = enc[b * Hn + j];
        __nv_bfloat16 hi = __float2bfloat16(h);
        __nv_bfloat16 lo = __float2bfloat16(h - __bfloat162float(hi));
        int ntile = b >> 3, n = b & 7;
        int ktile = j >> 4, c = j & 15;
        int lane2 = n * 4 + ((c & 7) >> 1);
        int reg  = c >> 3, pos = c & 1;
        uint32_t off = ((uint32_t)(ntile * NKT + ktile) * 32 + lane2) * 4 + reg * 2 + pos;
        g_hfrag_hi[0][off] = hi;
        g_hfrag_lo[0][off] = lo;
    }
}

// ---------------- init: decode use_tf, zero gates/counters/out[:,0,:] --------
__global__ void init_kernel(const unsigned char* tf_raw, float* out) {
    if (blockIdx.x == 0) {
        __shared__ int mode;
        if (threadIdx.x == 0) {
            int gt1 = 0, odd1 = 0;
            for (int i = 0; i < Sn; i++) {
                unsigned char v = tf_raw[i];
                if (v > 1) gt1 = 1;
                if (v == 1 && (i & 3)) odd1 = 1;
            }
            mode = gt1 ? 1 : (odd1 ? 0 : 1);
        }
        __syncthreads();
        if (threadIdx.x < Sn) {
            int t = threadIdx.x;
            int val;
            if (mode == 0) val = (tf_raw[t] != 0);
            else           val = (((const unsigned int*)tf_raw)[t] != 0u);
            g_tf[t] = val;
        }
        if (threadIdx.x < 16) g_cnt[threadIdx.x] = 0;
    }
    for (int i = blockIdx.x * blockDim.x + threadIdx.x; i < 16 * 128 * Bn;
         i += gridDim.x * blockDim.x)
        g_gates[i] = 0.0f;
    for (int i = blockIdx.x * blockDim.x + threadIdx.x; i < Bn * Vn;
         i += gridDim.x * blockDim.x) {
        int b = i / Vn, v = i - b * Vn;
        out[(size_t)b * Sn * Vn + v] = 0.0f;
    }
}

// ---------------- gatescell: tokens + split-K MMA + last-CTA cell epilogue ----
// grid (16, 6) x 256. slices 0-1: x-part (resolve tokens, smem x-frags);
// slices 2-5: h-part. Counter epilogue does cell update + h-frag emit.
__global__ __launch_bounds__(256) void gatescell_kernel(
    int k, const int* __restrict__ captions, const float* __restrict__ emb,
    const float* __restrict__ b_ih, const float* __restrict__ b_hh)
{
    __shared__ int tok_s[Bn];
    __shared__ __nv_bfloat16 sxh[8 * 8 * 32 * 4];   // 8192 bf16 = 16KB
    __shared__ __nv_bfloat16 sxl[8 * 8 * 32 * 4];
    __shared__ int is_last;

    int tid = threadIdx.x;
    int wid = tid >> 5, lane = tid & 31;
    int mw = wid & 3, nw = wid >> 2;
    int gid = lane >> 2, tig = lane & 3;
    int bid = blockIdx.x;
    int slice = blockIdx.y;
    bool xslice = (slice < 2);
    int rb = k & 1, wb = (k + 1) & 1;

    if (xslice) {
        // token resolution
        if (k == 0) {
            if (tid < Bn) tok_s[tid] = captions[tid * Sn + 0];
        } else {
            int b = tid >> 2, l4 = tid & 3;
            float bv = -3.4e38f; int bi = 0x7fffffff;
            for (int p = l4; p < NVB; p += 4) {
                float v = g_pval[b * NVB + p];
                int  ii = g_pidx[b * NVB + p];
                if (v > bv || (v == bv && ii < bi)) { bv = v; bi = ii; }
            }
            #pragma unroll
            for (int off = 2; off > 0; off >>= 1) {
                float ov = __shfl_down_sync(0xffffffffu, bv, off, 4);
                int   oi = __shfl_down_sync(0xffffffffu, bi, off, 4);
                if (ov > bv || (ov == bv && oi < bi)) { bv = ov; bi = oi; }
            }
            if (l4 == 0)
                tok_s[b] = g_tf[k] ? captions[b * Sn + k] : bi;
        }
        __syncthreads();
        // build x B-fragments for this slice's 128 k-dims
        for (int e = tid; e < Bn * 128; e += 256) {
            int b = e >> 7, kloc = e & 127;
            int tok = tok_s[b];
            int kg = slice * 128 + kloc;
            float x = (tok == 0) ? 0.0f : emb[(size_t)tok * En + kg];
            __nv_bfloat16 hi = __float2bfloat16(x);
            __nv_bfloat16 lo = __float2bfloat16(x - __bfloat162float(hi));
            int ntile = b >> 3, n = b & 7;
            int ktl = kloc >> 4, c = kloc & 15;
            int lane2 = n * 4 + ((c & 7) >> 1);
            int reg = c >> 3, pos = c & 1;
            uint32_t off = ((uint32_t)(ntile * 8 + ktl) * 32 + lane2) * 4 + reg * 2 + pos;
            sxh[off] = hi;
            sxl[off] = lo;
        }
        __syncthreads();
    }

    const uint4* wh4 = (const uint4*)g_wg_hi;
    const uint4* wl4 = (const uint4*)g_wg_lo;
    const uint2* xh2 = (const uint2*)sxh;
    const uint2* xl2 = (const uint2*)sxl;
    const uint2* hh2 = (const uint2*)g_hfrag_hi[rb];
    const uint2* hl2 = (const uint2*)g_hfrag_lo[rb];

    float acc[2][4][4];
    #pragma unroll
    for (int mt = 0; mt < 2; mt++)
        #pragma unroll
        for (int nt = 0; nt < 4; nt++)
            #pragma unroll
            for (int i = 0; i < 4; i++) acc[mt][nt][i] = 0.0f;

    int mt_g0 = bid * 8 + mw * 2;
    int kt0 = slice * GKS;

    #pragma unroll
    for (int kq = 0; kq < GKS; kq++) {
        int kt = kt0 + kq;
        uint4 ahi[2], alo[2];
        #pragma unroll
        for (int mt = 0; mt < 2; mt++) {
            size_t base = ((size_t)(mt_g0 + mt) * GKT + kt) * 32 + lane;
            ahi[mt] = wh4[base];
            alo[mt] = wl4[base];
        }
        #pragma unroll
        for (int nt = 0; nt < 4; nt++) {
            int nt_g = nw * 4 + nt;
            uint2 bhi, blo;
            if (xslice) {
                uint32_t bbase = (uint32_t)(nt_g * 8 + kq) * 32 + lane;
                bhi = xh2[bbase]; blo = xl2[bbase];
            } else {
                uint32_t bbase = (uint32_t)(nt_g * NKT + (kt - 16)) * 32 + lane;
                bhi = hh2[bbase]; blo = hl2[bbase];
            }
            #pragma unroll
            for (int mt = 0; mt < 2; mt++) {
                mma16816(acc[mt][nt], ahi[mt], bhi);
                mma16816(acc[mt][nt], ahi[mt], blo);
                mma16816(acc[mt][nt], alo[mt], bhi);
            }
        }
    }

    float* gbase = g_gates + bid * (128 * Bn);
    #pragma unroll
    for (int mt = 0; mt < 2; mt++) {
        int rl = mw * 32 + mt * 16 + gid;
        #pragma unroll
        for (int nt = 0; nt < 4; nt++) {
            int bl = (nw * 4 + nt) * 8 + tig * 2;
            atomicAdd(&gbase[rl * Bn + bl],           acc[mt][nt][0]);
            atomicAdd(&gbase[rl * Bn + bl + 1],       acc[mt][nt][1]);
            atomicAdd(&gbase[(rl + 8) * Bn + bl],     acc[mt][nt][2]);
            atomicAdd(&gbase[(rl + 8) * Bn + bl + 1], acc[mt][nt][3]);
        }
    }

    __threadfence();
    __syncthreads();
    if (tid == 0) {
        int prev = atomicAdd(&g_cnt[bid], 1);
        is_last = (prev == GSL - 1);
    }
    __syncthreads();
    if (!is_last) return;

    // last arrival: cell update for j in [bid*32, +32), all b
    #pragma unroll
    for (int it = 0; it < 8; it++) {
        int e = tid + it * 256;
        int jl = e >> 6, b = e & 63;
        int j = bid * 32 + jl;

        float gi = gbase[jl * Bn + b]         + b_ih[j]          + b_hh[j];
        float gf = gbase[(32 + jl) * Bn + b]  + b_ih[Hn + j]     + b_hh[Hn + j];
        float gg = gbase[(64 + jl) * Bn + b]  + b_ih[2 * Hn + j] + b_hh[2 * Hn + j];
        float go = gbase[(96 + jl) * Bn + b]  + b_ih[3 * Hn + j] + b_hh[3 * Hn + j];

        float c_old = (k == 0) ? 0.0f : g_c[b * Hn + j];
        float c = sigmoidf_(gf) * c_old + sigmoidf_(gi) * tanhf(gg);
        float h = sigmoidf_(go) * tanhf(c);
        g_c[b * Hn + j] = c;

        __nv_bfloat16 hi = __float2bfloat16(h);
        __nv_bfloat16 lo = __float2bfloat16(h - __bfloat162float(hi));
        int ntile = b >> 3, n = b & 7;
        int ktile = j >> 4, c2 = j & 15;
        int lane2 = n * 4 + ((c2 & 7) >> 1);
        int reg = c2 >> 3, pos = c2 & 1;
        uint32_t off = ((uint32_t)(ntile * NKT + ktile) * 32 + lane2) * 4 + reg * 2 + pos;
        g_hfrag_hi[wb][off] = hi;
        g_hfrag_lo[wb][off] = lo;
    }
    __syncthreads();
    float4 z4 = make_float4(0.f, 0.f, 0.f, 0.f);
    float4* gz = (float4*)gbase;
    #pragma unroll
    for (int it = 0; it < 8; it++)
        gz[tid + it * 256] = z4;
    if (tid == 0) g_cnt[bid] = 0;
}

// ---------------- logits GEMM: fp32 W frags, in-kernel hi/lo split ------------
__global__ __launch_bounds__(256) void logits_mma_kernel(
    int k, const float* __restrict__ fc_b, float* __restrict__ out)
{
    __shared__ float s_out[Bn][132];

    int tid = threadIdx.x;
    int wid = tid >> 5, lane = tid & 31;
    int mw = wid & 3, nw = wid >> 2;
    int gid = lane >> 2, tig = lane & 3;
    int wb = (k + 1) & 1;

    const float4* w4 = (const float4*)g_wfrag32;
    const uint2* hh2 = (const uint2*)g_hfrag_hi[wb];
    const uint2* hl2 = (const uint2*)g_hfrag_lo[wb];

    int mt_g0 = blockIdx.x * 8 + mw * 2;

    float acc[2][4][4];
    #pragma unroll
    for (int mt = 0; mt < 2; mt++)
        #pragma unroll
        for (int nt = 0; nt < 4; nt++)
            #pragma unroll
            for (int i = 0; i < 4; i++) acc[mt][nt][i] = 0.0f;

    for (int kt = 0; kt < NKT; kt++) {
        uint4 ahi[2], alo[2];
        #pragma unroll
        for (int mt = 0; mt < 2; mt++) {
            size_t base = (((size_t)(mt_g0 + mt) * NKT + kt) * 32 + lane) * 2;
            float4 a0 = w4[base];
            float4 a1 = w4[base + 1];
            uint32_t h0 = cvt2(a0.y, a0.x);
            uint32_t h1 = cvt2(a0.w, a0.z);
            uint32_t h2 = cvt2(a1.y, a1.x);
            uint32_t h3 = cvt2(a1.w, a1.z);
            ahi[mt] = make_uint4(h0, h1, h2, h3);
            alo[mt] = make_uint4(lo2(h0, a0.x, a0.y), lo2(h1, a0.z, a0.w),
                                 lo2(h2, a1.x, a1.y), lo2(h3, a1.z, a1.w));
        }
        #pragma unroll
        for (int nt = 0; nt < 4; nt++) {
            int nt_g = nw * 4 + nt;
            uint32_t bbase = (uint32_t)(nt_g * NKT + kt) * 32 + lane;
            uint2 bhi = hh2[bbase];
            uint2 blo = hl2[bbase];
            #pragma unroll
            for (int mt = 0; mt < 2; mt++) {
                mma16816(acc[mt][nt], ahi[mt], bhi);
                mma16816(acc[mt][nt], ahi[mt], blo);
                mma16816(acc[mt][nt], alo[mt], bhi);
            }
        }
    }

    #pragma unroll
    for (int mt = 0; mt < 2; mt++) {
        int vl = mw * 32 + mt * 16 + gid;
        #pragma unroll
        for (int nt = 0; nt < 4; nt++) {
            int bl = (nw * 4 + nt) * 8 + tig * 2;
            s_out[bl][vl]         = acc[mt][nt][0];
            s_out[bl + 1][vl]     = acc[mt][nt][1];
            s_out[bl][vl + 8]     = acc[mt][nt][2];
            s_out[bl + 1][vl + 8] = acc[mt][nt][3];
        }
    }
    __syncthreads();

    int v0g = blockIdx.x * 128;
    int t = k + 1;
    int b = tid >> 2, q = tid & 3;
    float* orow = out + ((size_t)b * Sn + t) * Vn + v0g + q * 32;
    float bv = -3.4e38f; int bi = 0x7fffffff;
    #pragma unroll
    for (int g8 = 0; g8 < 8; g8++) {
        float4 r;
        float* sp = &s_out[b][q * 32 + g8 * 4];
        const float* bp = fc_b + v0g + q * 32 + g8 * 4;
        r.x = sp[0] + bp[0];
        r.y = sp[1] + bp[1];
        r.z = sp[2] + bp[2];
        r.w = sp[3] + bp[3];
        *(float4*)(orow + g8 * 4) = r;
        int vb = v0g + q * 32 + g8 * 4;
        if (r.x > bv) { bv = r.x; bi = vb; }
        if (r.y > bv) { bv = r.y; bi = vb + 1; }
        if (r.z > bv) { bv = r.z; bi = vb + 2; }
        if (r.w > bv) { bv = r.w; bi = vb + 3; }
    }
    #pragma unroll
    for (int off = 2; off > 0; off >>= 1) {
        float ov = __shfl_down_sync(0xffffffffu, bv, off, 4);
        int   oi = __shfl_down_sync(0xffffffffu, bi, off, 4);
        if (ov > bv || (ov == bv && oi < bi)) { bv = ov; bi = oi; }
    }
    if (q == 0) {
        g_pval[b * NVB + blockIdx.x] = bv;
        g_pidx[b * NVB + blockIdx.x] = bi;
    }
}

// ---------------- launch ------------------------------------------------------
extern "C" void kernel_launch(void* const* d_in, const int* in_sizes, int n_in,
                              void* d_out, int out_size) {
    (void)in_sizes; (void)n_in; (void)out_size;
    const float*         enc  = (const float*)d_in[0];
    const int*           caps = (const int*)d_in[1];
    const unsigned char* tf   = (const unsigned char*)d_in[2];
    const float*         emb  = (const float*)d_in[3];
    const float*         W_ih = (const float*)d_in[4];
    const float*         W_hh = (const float*)d_in[5];
    const float*         b_ih = (const float*)d_in[6];
    const float*         b_hh = (const float*)d_in[7];
    const float*         fc_w = (const float*)d_in[8];
    const float*         fc_b = (const float*)d_in[9];
    float* out = (float*)d_out;

    init_kernel<<<512, 256>>>(tf, out);
    convert_w32_kernel<<<(Vn * Hn + 255) / 256, 256>>>(fc_w);
    convert_wg_kernel<<<(2048 * 768 + 255) / 256, 256>>>(W_ih, W_hh);
    encfrag_kernel<<<Bn, 256>>>(enc);
    dim3 gGrid(16, GSL);
    for (int k = 0; k < 63; k++) {
        gatescell_kernel<<<gGrid, 256>>>(k, caps, emb, b_ih, b_hh);
        logits_mma_kernel<<<250, 256>>>(k, fc_b, out);
    }
}

// round 16
// speedup vs baseline: 1.1669x; 1.1669x over previous
#include <cuda_runtime.h>
#include <cuda_bf16.h>
#include <math.h>
#include <stdint.h>

#define Bn 64
#define Hn 512
#define En 256
#define Vn 32000
#define Sn 64
#define NVB 250       /* Vn / 128 v-blocks in logits kernel */
#define NKT 32        /* logits k-tiles of 16 (Hn/16) */
#define GKT 48        /* gates  k-tiles of 16 ((En+Hn)/16) */
#define GSL 6         /* gates k-slices total (2 x + 4 h) */
#define GKS 8         /* k-tiles per slice */

// ---------------- persistent device state (no cudaMalloc allowed) ------------
__device__ float g_c[Bn * Hn];
__device__ float g_gates[16 * 128 * Bn];   // [bid][row_local][b] fp32 partials
__device__ int   g_cnt[16];                // split-K completion counters
__device__ float g_pval[Bn * NVB];
__device__ int   g_pidx[Bn * NVB];
__device__ int   g_tf[Sn];

// logits W fragments: [mtile(2000)][ktile(32)][lane(32)][8 bf16]
__device__ __nv_bfloat16 g_wfrag_hi[(size_t)Vn * Hn];
__device__ __nv_bfloat16 g_wfrag_lo[(size_t)Vn * Hn];
// gates W fragments: [bid(16)*8 + mtile][ktile(48)][lane(32)][8 bf16]
__device__ __nv_bfloat16 g_wg_hi[(size_t)128 * GKT * 32 * 8];
__device__ __nv_bfloat16 g_wg_lo[(size_t)128 * GKT * 32 * 8];
// h B-fragments, double buffered: [buf][ntile(8)][ktile(32)][lane(32)][4 bf16]
__device__ __nv_bfloat16 g_hfrag_hi[2][Bn * Hn];
__device__ __nv_bfloat16 g_hfrag_lo[2][Bn * Hn];

__device__ __forceinline__ float sigmoidf_(float x) {
    return 1.0f / (1.0f + expf(-x));
}

__device__ __forceinline__ void mma16816(float* c, const uint4& a, const uint2& b) {
    asm volatile(
        "mma.sync.aligned.m16n8k16.row.col.f32.bf16.bf16.f32 "
        "{%0,%1,%2,%3}, {%4,%5,%6,%7}, {%8,%9}, {%0,%1,%2,%3};"
        : "+f"(c[0]), "+f"(c[1]), "+f"(c[2]), "+f"(c[3])
        : "r"(a.x), "r"(a.y), "r"(a.z), "r"(a.w), "r"(b.x), "r"(b.y));
}

// ---------------- one-time conversions ---------------------------------------
__global__ void convert_w_kernel(const float* __restrict__ fc_w) {
    size_t idx = (size_t)blockIdx.x * blockDim.x + threadIdx.x;
    if (idx >= (size_t)Vn * Hn) return;
    int v = (int)(idx >> 9);
    int kg = (int)(idx & 511);
    float w = fc_w[idx];
    __nv_bfloat16 hi = __float2bfloat16(w);
    __nv_bfloat16 lo = __float2bfloat16(w - __bfloat162float(hi));
    int mtile = v >> 4, r = v & 15;
    int ktile = kg >> 4, c = kg & 15;
    int lane = (r & 7) * 4 + ((c & 7) >> 1);
    int reg  = (r >> 3) + 2 * (c >> 3);
    int pos  = c & 1;
    size_t off = ((size_t)(mtile * NKT + ktile) * 32 + lane) * 8 + reg * 2 + pos;
    g_wfrag_hi[off] = hi;
    g_wfrag_lo[off] = lo;
}

__global__ void convert_wg_kernel(const float* __restrict__ W_ih,
                                  const float* __restrict__ W_hh) {
    size_t idx = (size_t)blockIdx.x * blockDim.x + threadIdx.x;
    if (idx >= (size_t)2048 * 768) return;
    int R = (int)(idx / 768);
    int kc = (int)(idx % 768);
    float w = (kc < En) ? W_ih[(size_t)R * En + kc]
                        : W_hh[(size_t)R * Hn + (kc - En)];
    __nv_bfloat16 hi = __float2bfloat16(w);
    __nv_bfloat16 lo = __float2bfloat16(w - __bfloat162float(hi));
    int gate = R >> 9, j = R & 511;
    int bid = j >> 5;
    int rloc = gate * 32 + (j & 31);
    int mtile = bid * 8 + (rloc >> 4);
    int r16 = rloc & 15;
    int ktile = kc >> 4, c = kc & 15;
    int lane = (r16 & 7) * 4 + ((c & 7) >> 1);
    int reg  = (r16 >> 3) + 2 * (c >> 3);
    int pos  = c & 1;
    size_t off = ((size_t)(mtile * GKT + ktile) * 32 + lane) * 8 + reg * 2 + pos;
    g_wg_hi[off] = hi;
    g_wg_lo[off] = lo;
}

// one-time: h fragments from encoder_hidden into buffer 0
__global__ __launch_bounds__(256) void encfrag_kernel(const float* __restrict__ enc) {
    int b = blockIdx.x;
    int tid = threadIdx.x;
    #pragma unroll
    for (int q = 0; q < 2; q++) {
        int j = tid + q * 256;
        float h = enc[b * Hn + j];
        __nv_bfloat16 hi = __float2bfloat16(h);
        __nv_bfloat16 lo = __float2bfloat16(h - __bfloat162float(hi));
        int ntile = b >> 3, n = b & 7;
        int ktile = j >> 4, c = j & 15;
        int lane2 = n * 4 + ((c & 7) >> 1);
        int reg  = c >> 3, pos = c & 1;
        uint32_t off = ((uint32_t)(ntile * NKT + ktile) * 32 + lane2) * 4 + reg * 2 + pos;
        g_hfrag_hi[0][off] = hi;
        g_hfrag_lo[0][off] = lo;
    }
}

// ---------------- init: decode use_tf, zero gates/counters/out[:,0,:] --------
__global__ void init_kernel(const unsigned char* tf_raw, float* out) {
    if (blockIdx.x == 0) {
        __shared__ int mode;
        if (threadIdx.x == 0) {
            int gt1 = 0, odd1 = 0;
            for (int i = 0; i < Sn; i++) {
                unsigned char v = tf_raw[i];
                if (v > 1) gt1 = 1;
                if (v == 1 && (i & 3)) odd1 = 1;
            }
            mode = gt1 ? 1 : (odd1 ? 0 : 1);
        }
        __syncthreads();
        if (threadIdx.x < Sn) {
            int t = threadIdx.x;
            int val;
            if (mode == 0) val = (tf_raw[t] != 0);
            else           val = (((const unsigned int*)tf_raw)[t] != 0u);
            g_tf[t] = val;
        }
        if (threadIdx.x < 16) g_cnt[threadIdx.x] = 0;
    }
    for (int i = blockIdx.x * blockDim.x + threadIdx.x; i < 16 * 128 * Bn;
         i += gridDim.x * blockDim.x)
        g_gates[i] = 0.0f;
    for (int i = blockIdx.x * blockDim.x + threadIdx.x; i < Bn * Vn;
         i += gridDim.x * blockDim.x) {
        int b = i / Vn, v = i - b * Vn;
        out[(size_t)b * Sn * Vn + v] = 0.0f;
    }
}

// ---------------- gates h-part body (slices 2..5) -----------------------------
__device__ __forceinline__ void gates_h_body(int bid, int slice, int rb,
                                             int tid) {
    int wid = tid >> 5, lane = tid & 31;
    int mw = wid & 3, nw = wid >> 2;
    int gid = lane >> 2, tig = lane & 3;

    const uint4* wh4 = (const uint4*)g_wg_hi;
    const uint4* wl4 = (const uint4*)g_wg_lo;
    const uint2* hh2 = (const uint2*)g_hfrag_hi[rb];
    const uint2* hl2 = (const uint2*)g_hfrag_lo[rb];

    float acc[2][4][4];
    #pragma unroll
    for (int mt = 0; mt < 2; mt++)
        #pragma unroll
        for (int nt = 0; nt < 4; nt++)
            #pragma unroll
            for (int i = 0; i < 4; i++) acc[mt][nt][i] = 0.0f;

    int mt_g0 = bid * 8 + mw * 2;
    int kt0 = slice * GKS;

    #pragma unroll
    for (int kq = 0; kq < GKS; kq++) {
        int kt = kt0 + kq;
        uint4 ahi[2], alo[2];
        #pragma unroll
        for (int mt = 0; mt < 2; mt++) {
            size_t base = ((size_t)(mt_g0 + mt) * GKT + kt) * 32 + lane;
            ahi[mt] = wh4[base];
            alo[mt] = wl4[base];
        }
        #pragma unroll
        for (int nt = 0; nt < 4; nt++) {
            int nt_g = nw * 4 + nt;
            uint32_t bbase = (uint32_t)(nt_g * NKT + (kt - 16)) * 32 + lane;
            uint2 bhi = hh2[bbase];
            uint2 blo = hl2[bbase];
            #pragma unroll
            for (int mt = 0; mt < 2; mt++) {
                mma16816(acc[mt][nt], ahi[mt], bhi);
                mma16816(acc[mt][nt], ahi[mt], blo);
                mma16816(acc[mt][nt], alo[mt], bhi);
            }
        }
    }

    float* gbase = g_gates + bid * (128 * Bn);
    #pragma unroll
    for (int mt = 0; mt < 2; mt++) {
        int rl = mw * 32 + mt * 16 + gid;
        #pragma unroll
        for (int nt = 0; nt < 4; nt++) {
            int bl = (nw * 4 + nt) * 8 + tig * 2;
            atomicAdd(&gbase[rl * Bn + bl],           acc[mt][nt][0]);
            atomicAdd(&gbase[rl * Bn + bl + 1],       acc[mt][nt][1]);
            atomicAdd(&gbase[(rl + 8) * Bn + bl],     acc[mt][nt][2]);
            atomicAdd(&gbase[(rl + 8) * Bn + bl + 1], acc[mt][nt][3]);
        }
    }
    __threadfence();
    __syncthreads();
    if (tid == 0) atomicAdd(&g_cnt[bid], 1);
}

// standalone gates_h for step 0 (reads enc fragments, buffer 0)
__global__ __launch_bounds__(256) void gates_h0_kernel() {
    gates_h_body(blockIdx.x, 2 + blockIdx.y, 0, threadIdx.x);
}

// ---------------- gatesx: tokens + x-part MMA + cell epilogue -----------------
// grid (16, 2) x 256. CTA (bid, slice): x k-tiles [slice*8, +8).
__global__ __launch_bounds__(256) void gatesx_kernel(
    int k, const int* __restrict__ captions, const float* __restrict__ emb,
    const float* __restrict__ b_ih, const float* __restrict__ b_hh)
{
    __shared__ int tok_s[Bn];
    __shared__ __nv_bfloat16 sxh[8 * 8 * 32 * 4];   // 8192 bf16 = 16KB
    __shared__ __nv_bfloat16 sxl[8 * 8 * 32 * 4];
    __shared__ int is_last;

    int tid = threadIdx.x;
    int wid = tid >> 5, lane = tid & 31;
    int mw = wid & 3, nw = wid >> 2;
    int gid = lane >> 2, tig = lane & 3;
    int bid = blockIdx.x;
    int slice = blockIdx.y;          // 0 or 1
    int wb = (k + 1) & 1;

    // token resolution (redundant per CTA)
    if (k == 0) {
        if (tid < Bn) tok_s[tid] = captions[tid * Sn + 0];
    } else {
        int b = tid >> 2, l4 = tid & 3;
        float bv = -3.4e38f; int bi = 0x7fffffff;
        for (int p = l4; p < NVB; p += 4) {
            float v = g_pval[b * NVB + p];
            int  ii = g_pidx[b * NVB + p];
            if (v > bv || (v == bv && ii < bi)) { bv = v; bi = ii; }
        }
        #pragma unroll
        for (int off = 2; off > 0; off >>= 1) {
            float ov = __shfl_down_sync(0xffffffffu, bv, off, 4);
            int   oi = __shfl_down_sync(0xffffffffu, bi, off, 4);
            if (ov > bv || (ov == bv && oi < bi)) { bv = ov; bi = oi; }
        }
        if (l4 == 0)
            tok_s[b] = g_tf[k] ? captions[b * Sn + k] : bi;
    }
    __syncthreads();

    // build x B-fragments for this slice's 128 k-dims into smem
    for (int e = tid; e < Bn * 128; e += 256) {
        int b = e >> 7, kloc = e & 127;
        int tok = tok_s[b];
        int kg = slice * 128 + kloc;
        float x = (tok == 0) ? 0.0f : emb[(size_t)tok * En + kg];
        __nv_bfloat16 hi = __float2bfloat16(x);
        __nv_bfloat16 lo = __float2bfloat16(x - __bfloat162float(hi));
        int ntile = b >> 3, n = b & 7;
        int ktl = kloc >> 4, c = kloc & 15;
        int lane2 = n * 4 + ((c & 7) >> 1);
        int reg = c >> 3, pos = c & 1;
        uint32_t off = ((uint32_t)(ntile * 8 + ktl) * 32 + lane2) * 4 + reg * 2 + pos;
        sxh[off] = hi;
        sxl[off] = lo;
    }
    __syncthreads();

    const uint4* wh4 = (const uint4*)g_wg_hi;
    const uint4* wl4 = (const uint4*)g_wg_lo;
    const uint2* xh2 = (const uint2*)sxh;
    const uint2* xl2 = (const uint2*)sxl;

    float acc[2][4][4];
    #pragma unroll
    for (int mt = 0; mt < 2; mt++)
        #pragma unroll
        for (int nt = 0; nt < 4; nt++)
            #pragma unroll
            for (int i = 0; i < 4; i++) acc[mt][nt][i] = 0.0f;

    int mt_g0 = bid * 8 + mw * 2;
    int kt0 = slice * GKS;

    #pragma unroll
    for (int kq = 0; kq < GKS; kq++) {
        int kt = kt0 + kq;
        uint4 ahi[2], alo[2];
        #pragma unroll
        for (int mt = 0; mt < 2; mt++) {
            size_t base = ((size_t)(mt_g0 + mt) * GKT + kt) * 32 + lane;
            ahi[mt] = wh4[base];
            alo[mt] = wl4[base];
        }
        #pragma unroll
        for (int nt = 0; nt < 4; nt++) {
            int nt_g = nw * 4 + nt;
            uint32_t bbase = (uint32_t)(nt_g * 8 + kq) * 32 + lane;
            uint2 bhi = xh2[bbase];
            uint2 blo = xl2[bbase];
            #pragma unroll
            for (int mt = 0; mt < 2; mt++) {
                mma16816(acc[mt][nt], ahi[mt], bhi);
                mma16816(acc[mt][nt], ahi[mt], blo);
                mma16816(acc[mt][nt], alo[mt], bhi);
            }
        }
    }

    float* gbase = g_gates + bid * (128 * Bn);
    #pragma unroll
    for (int mt = 0; mt < 2; mt++) {
        int rl = mw * 32 + mt * 16 + gid;
        #pragma unroll
        for (int nt = 0; nt < 4; nt++) {
            int bl = (nw * 4 + nt) * 8 + tig * 2;
            atomicAdd(&gbase[rl * Bn + bl],           acc[mt][nt][0]);
            atomicAdd(&gbase[rl * Bn + bl + 1],       acc[mt][nt][1]);
            atomicAdd(&gbase[(rl + 8) * Bn + bl],     acc[mt][nt][2]);
            atomicAdd(&gbase[(rl + 8) * Bn + bl + 1], acc[mt][nt][3]);
        }
    }

    __threadfence();
    __syncthreads();
    if (tid == 0) {
        int prev = atomicAdd(&g_cnt[bid], 1);
        is_last = (prev == GSL - 1);
    }
    __syncthreads();
    if (!is_last) return;

    // last arrival: cell update for j in [bid*32, +32), all b
    #pragma unroll
    for (int it = 0; it < 8; it++) {
        int e = tid + it * 256;
        int jl = e >> 6, b = e & 63;
        int j = bid * 32 + jl;

        float gi = gbase[jl * Bn + b]         + b_ih[j]          + b_hh[j];
        float gf = gbase[(32 + jl) * Bn + b]  + b_ih[Hn + j]     + b_hh[Hn + j];
        float gg = gbase[(64 + jl) * Bn + b]  + b_ih[2 * Hn + j] + b_hh[2 * Hn + j];
        float go = gbase[(96 + jl) * Bn + b]  + b_ih[3 * Hn + j] + b_hh[3 * Hn + j];

        float c_old = (k == 0) ? 0.0f : g_c[b * Hn + j];
        float c = sigmoidf_(gf) * c_old + sigmoidf_(gi) * tanhf(gg);
        float h = sigmoidf_(go) * tanhf(c);
        g_c[b * Hn + j] = c;

        __nv_bfloat16 hi = __float2bfloat16(h);
        __nv_bfloat16 lo = __float2bfloat16(h - __bfloat162float(hi));
        int ntile = b >> 3, n = b & 7;
        int ktile = j >> 4, c2 = j & 15;
        int lane2 = n * 4 + ((c2 & 7) >> 1);
        int reg = c2 >> 3, pos = c2 & 1;
        uint32_t off = ((uint32_t)(ntile * NKT + ktile) * 32 + lane2) * 4 + reg * 2 + pos;
        g_hfrag_hi[wb][off] = hi;
        g_hfrag_lo[wb][off] = lo;
    }
    __syncthreads();
    float4 z4 = make_float4(0.f, 0.f, 0.f, 0.f);
    float4* gz = (float4*)gbase;
    #pragma unroll
    for (int it = 0; it < 8; it++)
        gz[tid + it * 256] = z4;
    if (tid == 0) g_cnt[bid] = 0;
}

// ---------------- logits GEMM + tail gates_h(k+1) in first 64 CTAs ------------
// grid 250 x 256 threads.
__global__ __launch_bounds__(256) void logits_mma_kernel(
    int k, int do_gh, const float* __restrict__ fc_b, float* __restrict__ out)
{
    __shared__ float s_out[Bn][132];

    int tid = threadIdx.x;
    int wid = tid >> 5, lane = tid & 31;
    int mw = wid & 3, nw = wid >> 2;
    int gid = lane >> 2, tig = lane & 3;
    int wb = (k + 1) & 1;

    const uint4* wh4 = (const uint4*)g_wfrag_hi;
    const uint4* wl4 = (const uint4*)g_wfrag_lo;
    const uint2* hh2 = (const uint2*)g_hfrag_hi[wb];
    const uint2* hl2 = (const uint2*)g_hfrag_lo[wb];

    int mt_g0 = blockIdx.x * 8 + mw * 2;

    float acc[2][4][4];
    #pragma unroll
    for (int mt = 0; mt < 2; mt++)
        #pragma unroll
        for (int nt = 0; nt < 4; nt++)
            #pragma unroll
            for (int i = 0; i < 4; i++) acc[mt][nt][i] = 0.0f;

    for (int kt = 0; kt < NKT; kt++) {
        uint4 ahi[2], alo[2];
        #pragma unroll
        for (int mt = 0; mt < 2; mt++) {
            size_t base = ((size_t)(mt_g0 + mt) * NKT + kt) * 32 + lane;
            ahi[mt] = wh4[base];
            alo[mt] = wl4[base];
        }
        #pragma unroll
        for (int nt = 0; nt < 4; nt++) {
            int nt_g = nw * 4 + nt;
            uint32_t bbase = (uint32_t)(nt_g * NKT + kt) * 32 + lane;
            uint2 bhi = hh2[bbase];
            uint2 blo = hl2[bbase];
            #pragma unroll
            for (int mt = 0; mt < 2; mt++) {
                mma16816(acc[mt][nt], ahi[mt], bhi);
                mma16816(acc[mt][nt], ahi[mt], blo);
                mma16816(acc[mt][nt], alo[mt], bhi);
            }
        }
    }

    #pragma unroll
    for (int mt = 0; mt < 2; mt++) {
        int vl = mw * 32 + mt * 16 + gid;
        #pragma unroll
        for (int nt = 0; nt < 4; nt++) {
            int bl = (nw * 4 + nt) * 8 + tig * 2;
            s_out[bl][vl]         = acc[mt][nt][0];
            s_out[bl + 1][vl]     = acc[mt][nt][1];
            s_out[bl][vl + 8]     = acc[mt][nt][2];
            s_out[bl + 1][vl + 8] = acc[mt][nt][3];
        }
    }
    __syncthreads();

    int v0g = blockIdx.x * 128;
    int t = k + 1;
    int b = tid >> 2, q = tid & 3;
    float* orow = out + ((size_t)b * Sn + t) * Vn + v0g + q * 32;
    float bv = -3.4e38f; int bi = 0x7fffffff;
    #pragma unroll
    for (int g8 = 0; g8 < 8; g8++) {
        float4 r;
        float* sp = &s_out[b][q * 32 + g8 * 4];
        const float* bp = fc_b + v0g + q * 32 + g8 * 4;
        r.x = sp[0] + bp[0];
        r.y = sp[1] + bp[1];
        r.z = sp[2] + bp[2];
        r.w = sp[3] + bp[3];
        *(float4*)(orow + g8 * 4) = r;
        int vb = v0g + q * 32 + g8 * 4;
        if (r.x > bv) { bv = r.x; bi = vb; }
        if (r.y > bv) { bv = r.y; bi = vb + 1; }
        if (r.z > bv) { bv = r.z; bi = vb + 2; }
        if (r.w > bv) { bv = r.w; bi = vb + 3; }
    }
    #pragma unroll
    for (int off = 2; off > 0; off >>= 1) {
        float ov = __shfl_down_sync(0xffffffffu, bv, off, 4);
        int   oi = __shfl_down_sync(0xffffffffu, bi, off, 4);
        if (ov > bv || (ov == bv && oi < bi)) { bv = ov; bi = oi; }
    }
    if (q == 0) {
        g_pval[b * NVB + blockIdx.x] = bv;
        g_pidx[b * NVB + blockIdx.x] = bi;
    }

    // tail work: gates_h for step k+1 (h(k+1) already available in buffer wb)
    if (do_gh && blockIdx.x < 64) {
        gates_h_body((int)(blockIdx.x & 15), 2 + (int)(blockIdx.x >> 4), wb, tid);
    }
}

// ---------------- launch ------------------------------------------------------
extern "C" void kernel_launch(void* const* d_in, const int* in_sizes, int n_in,
                              void* d_out, int out_size) {
    (void)in_sizes; (void)n_in; (void)out_size;
    const float*         enc  = (const float*)d_in[0];
    const int*           caps = (const int*)d_in[1];
    const unsigned char* tf   = (const unsigned char*)d_in[2];
    const float*         emb  = (const float*)d_in[3];
    const float*         W_ih = (const float*)d_in[4];
    const float*         W_hh = (const float*)d_in[5];
    const float*         b_ih = (const float*)d_in[6];
    const float*         b_hh = (const float*)d_in[7];
    const float*         fc_w = (const float*)d_in[8];
    const float*         fc_b = (const float*)d_in[9];
    float* out = (float*)d_out;

    init_kernel<<<512, 256>>>(tf, out);
    convert_w_kernel<<<(Vn * Hn + 255) / 256, 256>>>(fc_w);
    convert_wg_kernel<<<(2048 * 768 + 255) / 256, 256>>>(W_ih, W_hh);
    encfrag_kernel<<<Bn, 256>>>(enc);
    gates_h0_kernel<<<dim3(16, 4), 256>>>();
    for (int k = 0; k < 63; k++) {
        gatesx_kernel<<<dim3(16, 2), 256>>>(k, caps, emb, b_ih, b_hh);
        int do_gh = (k < 62) ? 1 : 0;
        logits_mma_kernel<<<250, 256>>>(k, do_gh, fc_b, out);
    }
}

// round 17
// speedup vs baseline: 1.2508x; 1.0719x over previous
#include <cuda_runtime.h>
#include <cuda_bf16.h>
#include <math.h>
#include <stdint.h>

#define Bn 64
#define Hn 512
#define En 256
#define Vn 32000
#define Sn 64
#define NVB 250       /* Vn / 128 v-blocks in logits kernel */
#define NKT 32        /* logits k-tiles of 16 (Hn/16) */
#define GKT 48        /* gates  k-tiles of 16 ((En+Hn)/16) */
#define GSL 6         /* gates k-slices total (2 x + 4 h) */
#define GKS 8         /* k-tiles per slice */

// ---------------- persistent device state (no cudaMalloc allowed) ------------
__device__ float g_c[Bn * Hn];
__device__ float g_gates[16 * 128 * Bn];   // [bid][row_local][b] fp32 partials
__device__ int   g_cnt[16];                // split-K completion counters
__device__ int   g_done;                   // logits completion counter
__device__ int   g_tail;                   // tail completion counter
__device__ float g_pval[Bn * NVB];
__device__ int   g_pidx[Bn * NVB];
__device__ int   g_tf[Sn];

// logits W fragments: [mtile(2000)][ktile(32)][lane(32)][8 bf16]
__device__ __nv_bfloat16 g_wfrag_hi[(size_t)Vn * Hn];
__device__ __nv_bfloat16 g_wfrag_lo[(size_t)Vn * Hn];
// gates W fragments: [bid(16)*8 + mtile][ktile(48)][lane(32)][8 bf16]
__device__ __nv_bfloat16 g_wg_hi[(size_t)128 * GKT * 32 * 8];
__device__ __nv_bfloat16 g_wg_lo[(size_t)128 * GKT * 32 * 8];
// h B-fragments, double buffered: [buf][ntile(8)][ktile(32)][lane(32)][4 bf16]
__device__ __nv_bfloat16 g_hfrag_hi[2][Bn * Hn];
__device__ __nv_bfloat16 g_hfrag_lo[2][Bn * Hn];

__device__ __forceinline__ float sigmoidf_(float x) {
    return 1.0f / (1.0f + expf(-x));
}

__device__ __forceinline__ void mma16816(float* c, const uint4& a, const uint2& b) {
    asm volatile(
        "mma.sync.aligned.m16n8k16.row.col.f32.bf16.bf16.f32 "
        "{%0,%1,%2,%3}, {%4,%5,%6,%7}, {%8,%9}, {%0,%1,%2,%3};"
        : "+f"(c[0]), "+f"(c[1]), "+f"(c[2]), "+f"(c[3])
        : "r"(a.x), "r"(a.y), "r"(a.z), "r"(a.w), "r"(b.x), "r"(b.y));
}

// ---------------- one-time conversions ---------------------------------------
__global__ void convert_w_kernel(const float* __restrict__ fc_w) {
    size_t idx = (size_t)blockIdx.x * blockDim.x + threadIdx.x;
    if (idx >= (size_t)Vn * Hn) return;
    int v = (int)(idx >> 9);
    int kg = (int)(idx & 511);
    float w = fc_w[idx];
    __nv_bfloat16 hi = __float2bfloat16(w);
    __nv_bfloat16 lo = __float2bfloat16(w - __bfloat162float(hi));
    int mtile = v >> 4, r = v & 15;
    int ktile = kg >> 4, c = kg & 15;
    int lane = (r & 7) * 4 + ((c & 7) >> 1);
    int reg  = (r >> 3) + 2 * (c >> 3);
    int pos  = c & 1;
    size_t off = ((size_t)(mtile * NKT + ktile) * 32 + lane) * 8 + reg * 2 + pos;
    g_wfrag_hi[off] = hi;
    g_wfrag_lo[off] = lo;
}

__global__ void convert_wg_kernel(const float* __restrict__ W_ih,
                                  const float* __restrict__ W_hh) {
    size_t idx = (size_t)blockIdx.x * blockDim.x + threadIdx.x;
    if (idx >= (size_t)2048 * 768) return;
    int R = (int)(idx / 768);
    int kc = (int)(idx % 768);
    float w = (kc < En) ? W_ih[(size_t)R * En + kc]
                        : W_hh[(size_t)R * Hn + (kc - En)];
    __nv_bfloat16 hi = __float2bfloat16(w);
    __nv_bfloat16 lo = __float2bfloat16(w - __bfloat162float(hi));
    int gate = R >> 9, j = R & 511;
    int bid = j >> 5;
    int rloc = gate * 32 + (j & 31);
    int mtile = bid * 8 + (rloc >> 4);
    int r16 = rloc & 15;
    int ktile = kc >> 4, c = kc & 15;
    int lane = (r16 & 7) * 4 + ((c & 7) >> 1);
    int reg  = (r16 >> 3) + 2 * (c >> 3);
    int pos  = c & 1;
    size_t off = ((size_t)(mtile * GKT + ktile) * 32 + lane) * 8 + reg * 2 + pos;
    g_wg_hi[off] = hi;
    g_wg_lo[off] = lo;
}

// one-time: h fragments from encoder_hidden into buffer 0
__global__ __launch_bounds__(256) void encfrag_kernel(const float* __restrict__ enc) {
    int b = blockIdx.x;
    int tid = threadIdx.x;
    #pragma unroll
    for (int q = 0; q < 2; q++) {
        int j = tid + q * 256;
        float h = enc[b * Hn + j];
        __nv_bfloat16 hi = __float2bfloat16(h);
        __nv_bfloat16 lo = __float2bfloat16(h - __bfloat162float(hi));
        int ntile = b >> 3, n = b & 7;
        int ktile = j >> 4, c = j & 15;
        int lane2 = n * 4 + ((c & 7) >> 1);
        int reg  = c >> 3, pos = c & 1;
        uint32_t off = ((uint32_t)(ntile * NKT + ktile) * 32 + lane2) * 4 + reg * 2 + pos;
        g_hfrag_hi[0][off] = hi;
        g_hfrag_lo[0][off] = lo;
    }
}

// ---------------- init ---------------------------------------------------------
__global__ void init_kernel(const unsigned char* tf_raw, float* out) {
    if (blockIdx.x == 0) {
        __shared__ int mode;
        if (threadIdx.x == 0) {
            int gt1 = 0, odd1 = 0;
            for (int i = 0; i < Sn; i++) {
                unsigned char v = tf_raw[i];
                if (v > 1) gt1 = 1;
                if (v == 1 && (i & 3)) odd1 = 1;
            }
            mode = gt1 ? 1 : (odd1 ? 0 : 1);
            g_done = 0;
            g_tail = 0;
        }
        __syncthreads();
        if (threadIdx.x < Sn) {
            int t = threadIdx.x;
            int val;
            if (mode == 0) val = (tf_raw[t] != 0);
            else           val = (((const unsigned int*)tf_raw)[t] != 0u);
            g_tf[t] = val;
        }
        if (threadIdx.x < 16) g_cnt[threadIdx.x] = 0;
    }
    for (int i = blockIdx.x * blockDim.x + threadIdx.x; i < 16 * 128 * Bn;
         i += gridDim.x * blockDim.x)
        g_gates[i] = 0.0f;
    for (int i = blockIdx.x * blockDim.x + threadIdx.x; i < Bn * Vn;
         i += gridDim.x * blockDim.x) {
        int b = i / Vn, v = i - b * Vn;
        out[(size_t)b * Sn * Vn + v] = 0.0f;
    }
}

// ---------------- gates step body (one split-K slice + maybe cell epilogue) ---
// kk: gates step index (reads h(kk) buffer kk&1, writes h(kk+1) buffer (kk+1)&1).
// For kk>0 x-slices: spins on g_done (logits partials of step kk-1), resolves token.
__device__ __forceinline__ void gates_step_body(
    int kk, int bid, int slice, int tid,
    __nv_bfloat16* sxh, __nv_bfloat16* sxl, int* tok_s, int* is_last_sh,
    const int* __restrict__ captions, const float* __restrict__ emb,
    const float* __restrict__ b_ih, const float* __restrict__ b_hh)
{
    int wid = tid >> 5, lane = tid & 31;
    int mw = wid & 3, nw = wid >> 2;
    int gid = lane >> 2, tig = lane & 3;
    bool xslice = (slice < 2);
    int rb = kk & 1, wb = (kk + 1) & 1;

    if (xslice) {
        if (kk > 0) {
            if (tid == 0) {
                while (atomicAdd(&g_done, 0) < 250) {}
            }
            __syncthreads();
            __threadfence();
            int b = tid >> 2, l4 = tid & 3;
            float bv = -3.4e38f; int bi = 0x7fffffff;
            for (int p = l4; p < NVB; p += 4) {
                float v = g_pval[b * NVB + p];
                int  ii = g_pidx[b * NVB + p];
                if (v > bv || (v == bv && ii < bi)) { bv = v; bi = ii; }
            }
            #pragma unroll
            for (int off = 2; off > 0; off >>= 1) {
                float ov = __shfl_down_sync(0xffffffffu, bv, off, 4);
                int   oi = __shfl_down_sync(0xffffffffu, bi, off, 4);
                if (ov > bv || (ov == bv && oi < bi)) { bv = ov; bi = oi; }
            }
            if (l4 == 0)
                tok_s[b] = g_tf[kk] ? captions[b * Sn + kk] : bi;
        } else {
            if (tid < Bn) tok_s[tid] = captions[tid * Sn + 0];
        }
        __syncthreads();
        // build x B-fragments for this slice's 128 k-dims into smem
        for (int e = tid; e < Bn * 128; e += 256) {
            int b = e >> 7, kloc = e & 127;
            int tok = tok_s[b];
            int kg = slice * 128 + kloc;
            float x = (tok == 0) ? 0.0f : emb[(size_t)tok * En + kg];
            __nv_bfloat16 hi = __float2bfloat16(x);
            __nv_bfloat16 lo = __float2bfloat16(x - __bfloat162float(hi));
            int ntile = b >> 3, n = b & 7;
            int ktl = kloc >> 4, c = kloc & 15;
            int lane2 = n * 4 + ((c & 7) >> 1);
            int reg = c >> 3, pos = c & 1;
            uint32_t off = ((uint32_t)(ntile * 8 + ktl) * 32 + lane2) * 4 + reg * 2 + pos;
            sxh[off] = hi;
            sxl[off] = lo;
        }
        __syncthreads();
    }

    const uint4* wh4 = (const uint4*)g_wg_hi;
    const uint4* wl4 = (const uint4*)g_wg_lo;
    const uint2* xh2 = (const uint2*)sxh;
    const uint2* xl2 = (const uint2*)sxl;
    const uint2* hh2 = (const uint2*)g_hfrag_hi[rb];
    const uint2* hl2 = (const uint2*)g_hfrag_lo[rb];

    float acc[2][4][4];
    #pragma unroll
    for (int mt = 0; mt < 2; mt++)
        #pragma unroll
        for (int nt = 0; nt < 4; nt++)
            #pragma unroll
            for (int i = 0; i < 4; i++) acc[mt][nt][i] = 0.0f;

    int mt_g0 = bid * 8 + mw * 2;
    int kt0 = slice * GKS;

    #pragma unroll
    for (int kq = 0; kq < GKS; kq++) {
        int kt = kt0 + kq;
        uint4 ahi[2], alo[2];
        #pragma unroll
        for (int mt = 0; mt < 2; mt++) {
            size_t base = ((size_t)(mt_g0 + mt) * GKT + kt) * 32 + lane;
            ahi[mt] = wh4[base];
            alo[mt] = wl4[base];
        }
        #pragma unroll
        for (int nt = 0; nt < 4; nt++) {
            int nt_g = nw * 4 + nt;
            uint2 bhi, blo;
            if (xslice) {
                uint32_t bbase = (uint32_t)(nt_g * 8 + kq) * 32 + lane;
                bhi = xh2[bbase]; blo = xl2[bbase];
            } else {
                uint32_t bbase = (uint32_t)(nt_g * NKT + (kt - 16)) * 32 + lane;
                bhi = hh2[bbase]; blo = hl2[bbase];
            }
            #pragma unroll
            for (int mt = 0; mt < 2; mt++) {
                mma16816(acc[mt][nt], ahi[mt], bhi);
                mma16816(acc[mt][nt], ahi[mt], blo);
                mma16816(acc[mt][nt], alo[mt], bhi);
            }
        }
    }

    float* gbase = g_gates + bid * (128 * Bn);
    #pragma unroll
    for (int mt = 0; mt < 2; mt++) {
        int rl = mw * 32 + mt * 16 + gid;
        #pragma unroll
        for (int nt = 0; nt < 4; nt++) {
            int bl = (nw * 4 + nt) * 8 + tig * 2;
            atomicAdd(&gbase[rl * Bn + bl],           acc[mt][nt][0]);
            atomicAdd(&gbase[rl * Bn + bl + 1],       acc[mt][nt][1]);
            atomicAdd(&gbase[(rl + 8) * Bn + bl],     acc[mt][nt][2]);
            atomicAdd(&gbase[(rl + 8) * Bn + bl + 1], acc[mt][nt][3]);
        }
    }

    __threadfence();
    __syncthreads();
    if (tid == 0) {
        int prev = atomicAdd(&g_cnt[bid], 1);
        *is_last_sh = (prev == GSL - 1);
    }
    __syncthreads();
    if (!*is_last_sh) return;

    // last arrival: cell update for j in [bid*32, +32), all b
    #pragma unroll
    for (int it = 0; it < 8; it++) {
        int e = tid + it * 256;
        int jl = e >> 6, b = e & 63;
        int j = bid * 32 + jl;

        float gi = gbase[jl * Bn + b]         + b_ih[j]          + b_hh[j];
        float gf = gbase[(32 + jl) * Bn + b]  + b_ih[Hn + j]     + b_hh[Hn + j];
        float gg = gbase[(64 + jl) * Bn + b]  + b_ih[2 * Hn + j] + b_hh[2 * Hn + j];
        float go = gbase[(96 + jl) * Bn + b]  + b_ih[3 * Hn + j] + b_hh[3 * Hn + j];

        float c_old = (kk == 0) ? 0.0f : g_c[b * Hn + j];
        float c = sigmoidf_(gf) * c_old + sigmoidf_(gi) * tanhf(gg);
        float h = sigmoidf_(go) * tanhf(c);
        g_c[b * Hn + j] = c;

        __nv_bfloat16 hi = __float2bfloat16(h);
        __nv_bfloat16 lo = __float2bfloat16(h - __bfloat162float(hi));
        int ntile = b >> 3, n = b & 7;
        int ktile = j >> 4, c2 = j & 15;
        int lane2 = n * 4 + ((c2 & 7) >> 1);
        int reg = c2 >> 3, pos = c2 & 1;
        uint32_t off = ((uint32_t)(ntile * NKT + ktile) * 32 + lane2) * 4 + reg * 2 + pos;
        g_hfrag_hi[wb][off] = hi;
        g_hfrag_lo[wb][off] = lo;
    }
    __syncthreads();
    float4 z4 = make_float4(0.f, 0.f, 0.f, 0.f);
    float4* gz = (float4*)gbase;
    #pragma unroll
    for (int it = 0; it < 8; it++)
        gz[tid + it * 256] = z4;
    if (tid == 0) g_cnt[bid] = 0;
}

// ---------------- standalone gates for step 0 ---------------------------------
__global__ __launch_bounds__(256) void gatescell0_kernel(
    const int* __restrict__ captions, const float* __restrict__ emb,
    const float* __restrict__ b_ih, const float* __restrict__ b_hh)
{
    __shared__ __nv_bfloat16 sxh[8192];
    __shared__ __nv_bfloat16 sxl[8192];
    __shared__ int tok_s[Bn];
    __shared__ int is_last_sh;
    gates_step_body(0, blockIdx.x, blockIdx.y, threadIdx.x,
                    sxh, sxl, tok_s, &is_last_sh, captions, emb, b_ih, b_hh);
}

// ---------------- fused: logits(k) + full gates(k+1) + cell -------------------
// grid 250 x 256. All CTAs do one logits tile; blocks 0..95 then do one gates
// slice for step k+1 (h-slices need no wait; x-slices spin for argmax).
__global__ __launch_bounds__(256) void fused_kernel(
    int k, const int* __restrict__ captions, const float* __restrict__ emb,
    const float* __restrict__ b_ih, const float* __restrict__ b_hh,
    const float* __restrict__ fc_b, float* __restrict__ out)
{
    __shared__ __align__(16) char sbuf[33792];
    __shared__ int is_last_sh;
    float (*s_out)[132] = (float (*)[132])sbuf;

    int tid = threadIdx.x;
    int wid = tid >> 5, lane = tid & 31;
    int mw = wid & 3, nw = wid >> 2;
    int gid = lane >> 2, tig = lane & 3;
    int wb = (k + 1) & 1;

    const uint4* wh4 = (const uint4*)g_wfrag_hi;
    const uint4* wl4 = (const uint4*)g_wfrag_lo;
    const uint2* hh2 = (const uint2*)g_hfrag_hi[wb];
    const uint2* hl2 = (const uint2*)g_hfrag_lo[wb];

    int mt_g0 = blockIdx.x * 8 + mw * 2;

    float acc[2][4][4];
    #pragma unroll
    for (int mt = 0; mt < 2; mt++)
        #pragma unroll
        for (int nt = 0; nt < 4; nt++)
            #pragma unroll
            for (int i = 0; i < 4; i++) acc[mt][nt][i] = 0.0f;

    for (int kt = 0; kt < NKT; kt++) {
        uint4 ahi[2], alo[2];
        #pragma unroll
        for (int mt = 0; mt < 2; mt++) {
            size_t base = ((size_t)(mt_g0 + mt) * NKT + kt) * 32 + lane;
            ahi[mt] = wh4[base];
            alo[mt] = wl4[base];
        }
        #pragma unroll
        for (int nt = 0; nt < 4; nt++) {
            int nt_g = nw * 4 + nt;
            uint32_t bbase = (uint32_t)(nt_g * NKT + kt) * 32 + lane;
            uint2 bhi = hh2[bbase];
            uint2 blo = hl2[bbase];
            #pragma unroll
            for (int mt = 0; mt < 2; mt++) {
                mma16816(acc[mt][nt], ahi[mt], bhi);
                mma16816(acc[mt][nt], ahi[mt], blo);
                mma16816(acc[mt][nt], alo[mt], bhi);
            }
        }
    }

    #pragma unroll
    for (int mt = 0; mt < 2; mt++) {
        int vl = mw * 32 + mt * 16 + gid;
        #pragma unroll
        for (int nt = 0; nt < 4; nt++) {
            int bl = (nw * 4 + nt) * 8 + tig * 2;
            s_out[bl][vl]         = acc[mt][nt][0];
            s_out[bl + 1][vl]     = acc[mt][nt][1];
            s_out[bl][vl + 8]     = acc[mt][nt][2];
            s_out[bl + 1][vl + 8] = acc[mt][nt][3];
        }
    }
    __syncthreads();

    {
        int v0g = blockIdx.x * 128;
        int t = k + 1;
        int b = tid >> 2, q = tid & 3;
        float* orow = out + ((size_t)b * Sn + t) * Vn + v0g + q * 32;
        float bv = -3.4e38f; int bi = 0x7fffffff;
        #pragma unroll
        for (int g8 = 0; g8 < 8; g8++) {
            float4 r;
            float* sp = &s_out[b][q * 32 + g8 * 4];
            const float* bp = fc_b + v0g + q * 32 + g8 * 4;
            r.x = sp[0] + bp[0];
            r.y = sp[1] + bp[1];
            r.z = sp[2] + bp[2];
            r.w = sp[3] + bp[3];
            *(float4*)(orow + g8 * 4) = r;
            int vb = v0g + q * 32 + g8 * 4;
            if (r.x > bv) { bv = r.x; bi = vb; }
            if (r.y > bv) { bv = r.y; bi = vb + 1; }
            if (r.z > bv) { bv = r.z; bi = vb + 2; }
            if (r.w > bv) { bv = r.w; bi = vb + 3; }
        }
        #pragma unroll
        for (int off = 2; off > 0; off >>= 1) {
            float ov = __shfl_down_sync(0xffffffffu, bv, off, 4);
            int   oi = __shfl_down_sync(0xffffffffu, bi, off, 4);
            if (ov > bv || (ov == bv && oi < bi)) { bv = ov; bi = oi; }
        }
        if (q == 0) {
            g_pval[b * NVB + blockIdx.x] = bv;
            g_pidx[b * NVB + blockIdx.x] = bi;
        }
    }

    // publish completion (partials visible before count)
    __threadfence();
    __syncthreads();
    if (tid == 0) atomicAdd(&g_done, 1);
    if (blockIdx.x >= 96) return;

    // ---- tail: one gates slice for step k+1 ----
    __nv_bfloat16* sxh = (__nv_bfloat16*)sbuf;
    __nv_bfloat16* sxl = sxh + 8192;
    int* tok_s = (int*)(sxh + 16384);
    int gbid = blockIdx.x & 15;
    int slice = blockIdx.x >> 4;          // 0..5
    __syncthreads();                       // s_out reads done before smem reuse

    gates_step_body(k + 1, gbid, slice, tid, sxh, sxl, tok_s, &is_last_sh,
                    captions, emb, b_ih, b_hh);

    // reset global counters once all tail CTAs are past their work
    if (tid == 0) {
        int t = atomicAdd(&g_tail, 1);
        if (t == 95) {
            g_done = 0;
            g_tail = 0;
            __threadfence();
        }
    }
}

// ---------------- launch ------------------------------------------------------
extern "C" void kernel_launch(void* const* d_in, const int* in_sizes, int n_in,
                              void* d_out, int out_size) {
    (void)in_sizes; (void)n_in; (void)out_size;
    const float*         enc  = (const float*)d_in[0];
    const int*           caps = (const int*)d_in[1];
    const unsigned char* tf   = (const unsigned char*)d_in[2];
    const float*         emb  = (const float*)d_in[3];
    const float*         W_ih = (const float*)d_in[4];
    const float*         W_hh = (const float*)d_in[5];
    const float*         b_ih = (const float*)d_in[6];
    const float*         b_hh = (const float*)d_in[7];
    const float*         fc_w = (const float*)d_in[8];
    const float*         fc_b = (const float*)d_in[9];
    float* out = (float*)d_out;

    init_kernel<<<512, 256>>>(tf, out);
    convert_w_kernel<<<(Vn * Hn + 255) / 256, 256>>>(fc_w);
    convert_wg_kernel<<<(2048 * 768 + 255) / 256, 256>>>(W_ih, W_hh);
    encfrag_kernel<<<Bn, 256>>>(enc);
    gatescell0_kernel<<<dim3(16, GSL), 256>>>(caps, emb, b_ih, b_hh);
    for (int k = 0; k < 63; k++) {
        fused_kernel<<<250, 256>>>(k, caps, emb, b_ih, b_hh, fc_b, out);
    }
}